// round 11
// baseline (speedup 1.0000x reference)
#include <cuda_runtime.h>
#include <cuda_bf16.h>
#include <cstdint>

#define TSEQ  512
#define BATCH 128
#define HID   1024
#define NLAY  4
#define BH    (BATCH*HID)
#define KTOT  2048              // K = concat(cur, hprev)
#define KC    128               // K per chunk (2 sub-tiles of 64 cols)
#define NCH   (KTOT/KC)         // 16 chunks
#define SUBB  8192              // 64 rows x 128 B sub-tile
#define TILEB (2*SUBB)          // one operand tile per chunk: 16 KB
#define STAGEB (4*TILEB)        // Ah, Al, Wh, Wl = 64 KB / stage
#define STAGES 3
#define DYN_SMEM (STAGES*STAGEB + 256)

// ---------------- static device buffers ----------------
__device__ __align__(256) __nv_bfloat16 g_xhi[(size_t)TSEQ*BH];
__device__ __align__(256) __nv_bfloat16 g_xlo[(size_t)TSEQ*BH];
__device__ __align__(256) __nv_bfloat16 g_rhi[NLAY*2*BH];             // hidden ring hi [layer][t&1]
__device__ __align__(256) __nv_bfloat16 g_rlo[NLAY*2*BH];             // hidden ring lo
__device__ __align__(256) __nv_bfloat16 g_whi[(size_t)NLAY*HID*KTOT]; // Wcat=[W_ih;W_hh] hi, K-major
__device__ __align__(256) __nv_bfloat16 g_wlo[(size_t)NLAY*HID*KTOT];

// ---------------- PTX helpers (baseline sm_80-level: safe on compute_103) -----
__device__ __forceinline__ unsigned smem_u32(const void* p) {
    unsigned a;
    asm("{ .reg .u64 t; cvta.to.shared.u64 t, %1; cvt.u32.u64 %0, t; }" : "=r"(a) : "l"(p));
    return a;
}
__device__ __forceinline__ void cp_async16(unsigned s, const void* g) {
    asm volatile("cp.async.ca.shared.global [%0], [%1], 16;\n" :: "r"(s), "l"(g));
}
__device__ __forceinline__ void cp_commit() { asm volatile("cp.async.commit_group;\n" ::: "memory"); }
template<int N>
__device__ __forceinline__ void cp_wait() { asm volatile("cp.async.wait_group %0;\n" :: "n"(N) : "memory"); }

__device__ __forceinline__ void ldsm4(unsigned& r0, unsigned& r1, unsigned& r2, unsigned& r3, unsigned a) {
    asm volatile("ldmatrix.sync.aligned.m8n8.x4.shared.b16 {%0,%1,%2,%3}, [%4];"
                 : "=r"(r0), "=r"(r1), "=r"(r2), "=r"(r3) : "r"(a));
}
__device__ __forceinline__ void mma16816(float4& c, const unsigned* a, unsigned b0, unsigned b1) {
    asm volatile("mma.sync.aligned.m16n8k16.row.col.f32.bf16.bf16.f32 "
                 "{%0,%1,%2,%3}, {%4,%5,%6,%7}, {%8,%9}, {%0,%1,%2,%3};"
                 : "+f"(c.x), "+f"(c.y), "+f"(c.z), "+f"(c.w)
                 : "r"(a[0]), "r"(a[1]), "r"(a[2]), "r"(a[3]), "r"(b0), "r"(b1));
}

// ---------------- split-fp32 conversion kernels ----------------
__global__ void conv_x(const float* __restrict__ x) {
    size_t i = (size_t)blockIdx.x * blockDim.x + threadIdx.x;
    if (i >= (size_t)TSEQ * BH) return;
    float v = x[i];
    __nv_bfloat16 h = __float2bfloat16(v);
    g_xhi[i] = h;
    g_xlo[i] = __float2bfloat16(v - __bfloat162float(h));
}
__global__ void conv_w(const float* __restrict__ Wih, const float* __restrict__ Whh) {
    size_t i = (size_t)blockIdx.x * blockDim.x + threadIdx.x;
    if (i >= (size_t)NLAY * HID * KTOT) return;
    int k = (int)(i & (KTOT - 1));
    size_t ln = i >> 11;                          // layer*HID + n
    float v = (k < HID) ? Wih[ln * HID + k] : Whh[ln * HID + (k - HID)];
    __nv_bfloat16 h = __float2bfloat16(v);
    g_whi[i] = h;
    g_wlo[i] = __float2bfloat16(v - __bfloat162float(h));
}

// fragment set for one kk (k16 slice): A hi/lo (2 m-frags), W hi/lo (2 ldsm = 4 n8-frags)
struct Frag {
    unsigned ah[2][4], al[2][4], wh[2][4], wl[2][4];
};

// ---------------- wavefront kernel ----------------
// 128 threads, 4 warps, warp-tile 32x32, CTA tile 64x64, 3-stage cp.async (KC=128),
// hand-scheduled kk software pipeline (volatile asm order == SASS order).
__global__ void __launch_bounds__(128, 1)
rnn_wave_mma(int s, const float* __restrict__ bih, const float* __restrict__ bhh,
             float* __restrict__ out)
{
    const int layer = blockIdx.y;
    const int t = s - layer;
    if (t < 0 || t >= TSEQ) return;

    const int mt = blockIdx.x >> 4;        // 0..1
    const int nt = blockIdx.x & 15;        // 0..15
    const int m0 = mt * 64;
    const int n0 = nt * 64;

    extern __shared__ __align__(16) char dynsm[];
    const unsigned dbase = (smem_u32(dynsm) + 127) & ~127u;

    const int tid  = threadIdx.x;
    const int wid  = tid >> 5;
    const int lane = tid & 31;
    const int wm   = wid >> 1;             // warp M offset 32*wm
    const int wn   = wid & 1;              // warp N offset 32*wn

    // ---- source pointers ----
    const __nv_bfloat16* curhi = (layer == 0) ? g_xhi + (size_t)t * BH
                                              : g_rhi + (size_t)((layer-1)*2 + (t & 1)) * BH;
    const __nv_bfloat16* curlo = (layer == 0) ? g_xlo + (size_t)t * BH
                                              : g_rlo + (size_t)((layer-1)*2 + (t & 1)) * BH;
    const __nv_bfloat16* phi = g_rhi + (size_t)(layer*2 + ((t-1) & 1)) * BH;
    const __nv_bfloat16* plo = g_rlo + (size_t)(layer*2 + ((t-1) & 1)) * BH;
    const __nv_bfloat16* whi = g_whi + (size_t)layer * HID * KTOT;
    const __nv_bfloat16* wlo = g_wlo + (size_t)layer * HID * KTOT;

    const int nChunks = (t == 0) ? (NCH / 2) : NCH;   // KC=128 divides HID: no straddle

    // ---- producer addressing: 16B granules, XOR swizzle within 64x128B sub-tile ----
    const int prow = tid >> 3;             // 0..15
    const int pg   = tid & 7;
    const unsigned so0 = (unsigned)(prow*128 + ((pg ^ (prow & 7)) << 4));

    auto issue_chunk = [&](int c, int buf) {
        const unsigned sb = dbase + buf * STAGEB;
        const int k0 = c * KC;
        const __nv_bfloat16 *ah, *al; int koff;
        if (k0 < HID) { ah = curhi; al = curlo; koff = k0; }
        else          { ah = phi;   al = plo;   koff = k0 - HID; }
        #pragma unroll
        for (int sub = 0; sub < 2; sub++) {
            const unsigned ss = sb + sub * SUBB;
            const int ks = koff + sub * 64;
            const int kw = k0 + sub * 64;
            #pragma unroll
            for (int i = 0; i < 4; i++) {
                const int row = prow + 16*i;
                const unsigned so = so0 + 2048u*i;
                cp_async16(ss + 0*TILEB + so, ah  + (size_t)(m0+row)*HID + ks + pg*8);
                cp_async16(ss + 1*TILEB + so, al  + (size_t)(m0+row)*HID + ks + pg*8);
                cp_async16(ss + 2*TILEB + so, whi + (size_t)(n0+row)*KTOT + kw + pg*8);
                cp_async16(ss + 3*TILEB + so, wlo + (size_t)(n0+row)*KTOT + kw + pg*8);
            }
        }
        cp_commit();
    };

    // ---- ldmatrix lane addressing ----
    const int x7 = lane & 7;
    const int asel = lane >> 4;
    const unsigned aRowOff0 = (unsigned)((wm*32 +      (lane & 15)) * 128);
    const unsigned aRowOff1 = (unsigned)((wm*32 + 16 + (lane & 15)) * 128);
    const int brow_in = (lane & 7) + ((lane & 16) >> 1);
    const int bsel = (lane >> 3) & 1;
    const unsigned bRowOff0 = (unsigned)((wn*32 +      brow_in) * 128);
    const unsigned bRowOff1 = (unsigned)((wn*32 + 16 + brow_in) * 128);

    float4 acc[2][4];
    #pragma unroll
    for (int mi = 0; mi < 2; mi++)
        #pragma unroll
        for (int nf = 0; nf < 4; nf++) acc[mi][nf] = make_float4(0.f, 0.f, 0.f, 0.f);

    // load helpers for kk (0..7): sub-tile kk>>2, inner k16 index kk&3
    auto ldA = [&](unsigned sb, int kk, Frag& f) {
        const unsigned ss = sb + (unsigned)(kk >> 2) * SUBB;
        const int ki = kk & 3;
        const unsigned axor = (unsigned)((((ki)*2 + asel) ^ x7) << 4);
        ldsm4(f.ah[0][0], f.ah[0][1], f.ah[0][2], f.ah[0][3], ss + 0*TILEB + aRowOff0 + axor);
        ldsm4(f.ah[1][0], f.ah[1][1], f.ah[1][2], f.ah[1][3], ss + 0*TILEB + aRowOff1 + axor);
        ldsm4(f.al[0][0], f.al[0][1], f.al[0][2], f.al[0][3], ss + 1*TILEB + aRowOff0 + axor);
        ldsm4(f.al[1][0], f.al[1][1], f.al[1][2], f.al[1][3], ss + 1*TILEB + aRowOff1 + axor);
    };
    auto ldW = [&](unsigned sb, int kk, Frag& f) {
        const unsigned ss = sb + (unsigned)(kk >> 2) * SUBB;
        const int ki = kk & 3;
        const unsigned bxor = (unsigned)((((ki)*2 + bsel) ^ x7) << 4);
        ldsm4(f.wh[0][0], f.wh[0][1], f.wh[0][2], f.wh[0][3], ss + 2*TILEB + bRowOff0 + bxor);
        ldsm4(f.wh[1][0], f.wh[1][1], f.wh[1][2], f.wh[1][3], ss + 2*TILEB + bRowOff1 + bxor);
        ldsm4(f.wl[0][0], f.wl[0][1], f.wl[0][2], f.wl[0][3], ss + 3*TILEB + bRowOff0 + bxor);
        ldsm4(f.wl[1][0], f.wl[1][1], f.wl[1][2], f.wl[1][3], ss + 3*TILEB + bRowOff1 + bxor);
    };
    auto pass = [&](const unsigned a[2][4], const unsigned w[2][4]) {
        #pragma unroll
        for (int mi = 0; mi < 2; mi++)
            #pragma unroll
            for (int nf = 0; nf < 4; nf++)
                mma16816(acc[mi][nf], a[mi], w[nf>>1][(nf&1)*2], w[nf>>1][(nf&1)*2+1]);
    };

    // hand-scheduled chunk: preload kk+1 fragments BETWEEN the MMA passes of kk
    // (volatile asm keeps this order in SASS: LDSM issues fill acc-RAW gaps,
    //  and each LDSM batch has ~2 passes of MMA issue before its consumer).
    Frag fr[2];
    auto compute_chunk = [&](int buf) {
        const unsigned sb = dbase + buf * STAGEB;
        ldA(sb, 0, fr[0]);
        ldW(sb, 0, fr[0]);
        #pragma unroll
        for (int kk = 0; kk < 8; kk++) {
            Frag& c = fr[kk & 1];
            Frag& n = fr[(kk + 1) & 1];
            pass(c.ah, c.wh);                      // pass 1: hi*hi
            if (kk < 7) ldA(sb, kk + 1, n);
            pass(c.ah, c.wl);                      // pass 2: hi*lo
            if (kk < 7) ldW(sb, kk + 1, n);
            pass(c.al, c.wh);                      // pass 3: lo*hi
        }
    };

    // ---- 3-stage pipeline, one barrier per chunk ----
    issue_chunk(0, 0);
    issue_chunk(1, 1);
    for (int c = 0; c < nChunks; c++) {
        if (c + 1 < nChunks) cp_wait<1>();   // chunk c landed (c+1 may be in flight)
        else                 cp_wait<0>();
        __syncthreads();                      // chunk c visible; stage (c+2)%3 free (compute c-1 done)
        if (c + 2 < nChunks) issue_chunk(c + 2, (c + 2) % STAGES);
        compute_chunk(c % STAGES);
    }

    // ---- epilogue: bias + tanh, split hi/lo to ring, fp32 to out for top layer ----
    const size_t rb = (size_t)(layer*2 + (t & 1)) * BH;
    #pragma unroll
    for (int mi = 0; mi < 2; mi++) {
        const int mlo = m0 + wm*32 + mi*16 + (lane >> 2);
        #pragma unroll
        for (int nf = 0; nf < 4; nf++) {
            const int n = n0 + wn*32 + nf*8 + (lane & 3)*2;
            const float b0 = bih[layer*HID + n]     + bhh[layer*HID + n];
            const float b1 = bih[layer*HID + n + 1] + bhh[layer*HID + n + 1];
            const float v00 = tanhf(acc[mi][nf].x + b0);
            const float v01 = tanhf(acc[mi][nf].y + b1);
            const float v10 = tanhf(acc[mi][nf].z + b0);
            const float v11 = tanhf(acc[mi][nf].w + b1);
            #pragma unroll
            for (int rh = 0; rh < 2; rh++) {
                const int m = mlo + rh*8;
                const float va = rh ? v10 : v00;
                const float vb = rh ? v11 : v01;
                const __nv_bfloat16 ha = __float2bfloat16(va);
                const __nv_bfloat16 hb = __float2bfloat16(vb);
                const __nv_bfloat16 la = __float2bfloat16(va - __bfloat162float(ha));
                const __nv_bfloat16 lb = __float2bfloat16(vb - __bfloat162float(hb));
                const unsigned hpack = (unsigned)__bfloat16_as_ushort(ha) |
                                       ((unsigned)__bfloat16_as_ushort(hb) << 16);
                const unsigned lpack = (unsigned)__bfloat16_as_ushort(la) |
                                       ((unsigned)__bfloat16_as_ushort(lb) << 16);
                *reinterpret_cast<unsigned*>(&g_rhi[rb + (size_t)m*HID + n]) = hpack;
                *reinterpret_cast<unsigned*>(&g_rlo[rb + (size_t)m*HID + n]) = lpack;
                if (layer == NLAY - 1) {
                    float2 o = make_float2(va, vb);
                    *reinterpret_cast<float2*>(&out[(size_t)t*BH + (size_t)m*HID + n]) = o;
                }
            }
        }
    }
}

extern "C" void kernel_launch(void* const* d_in, const int* in_sizes, int n_in,
                              void* d_out, int out_size) {
    const float* x   = (const float*)d_in[0];
    const float* Wih = (const float*)d_in[1];
    const float* Whh = (const float*)d_in[2];
    const float* bih = (const float*)d_in[3];
    const float* bhh = (const float*)d_in[4];
    float* out = (float*)d_out;

    cudaFuncSetAttribute(rnn_wave_mma, cudaFuncAttributeMaxDynamicSharedMemorySize, DYN_SMEM);

    // One-time (per replay) split fp32 -> bf16 hi/lo
    conv_x<<<(unsigned)(((size_t)TSEQ*BH + 255) / 256), 256>>>(x);
    conv_w<<<(unsigned)(((size_t)NLAY*HID*KTOT + 255) / 256), 256>>>(Wih, Whh);

    // Wavefront s = t + layer: 515 sequential launches; kernel boundaries = sync.
    const dim3 grid(32, NLAY);
    for (int s = 0; s < TSEQ + NLAY - 1; s++) {
        rnn_wave_mma<<<grid, 128, DYN_SMEM>>>(s, bih, bhh, out);
    }
}